// round 1
// baseline (speedup 1.0000x reference)
#include <cuda_runtime.h>
#include <cstdint>

// Problem constants (fixed by the reference generator)
#define NPTS        2000000
#define NUM_PTS3D   500000
#define NUM_GROUPS  10000
#define NUM_POS     8
#define NUM_CAMS    8

// Scratch: composed pose table (80000 x {t(float4), q(float4)}) = 2.56 MB
// and padded 3D points (500000 x float4) = 8 MB. Both L2-resident.
__device__ float4 g_comp[NUM_GROUPS * NUM_POS * 2];
__device__ float4 g_pts[NUM_PTS3D];

__device__ __forceinline__ float3 f3cross(float3 a, float3 b) {
    return make_float3(a.y * b.z - a.z * b.y,
                       a.z * b.x - a.x * b.z,
                       a.x * b.y - a.y * b.x);
}

// Pad points_3d [NUM_PTS3D,3] -> float4 table
__global__ __launch_bounds__(256) void pad_points_kernel(const float* __restrict__ p3d) {
    int i = blockIdx.x * blockDim.x + threadIdx.x;
    if (i >= NUM_PTS3D) return;
    const float* p = p3d + 3 * i;
    g_pts[i] = make_float4(p[0], p[1], p[2], 0.0f);
}

// Compose ref (per-group) and rel (per-member) SE3 poses.
// pose layout: [tx,ty,tz, qx,qy,qz,qw], quats Hamilton [x,y,z,w].
// t = rel.t + rot(rel.q, ref.t) ;  q = rel.q * ref.q
__global__ __launch_bounds__(256) void compose_kernel(const float* __restrict__ ref_poses,
                                                      const float* __restrict__ rel_poses) {
    int i = blockIdx.x * blockDim.x + threadIdx.x;
    if (i >= NUM_GROUPS * NUM_POS) return;
    int g = i >> 3;          // i / NUM_POS
    int m = i & 7;           // i % NUM_POS
    const float* R = ref_poses + g * 7;
    const float* L = rel_poses + m * 7;

    float3 rt = make_float3(R[0], R[1], R[2]);
    float4 rq = make_float4(R[3], R[4], R[5], R[6]);
    float3 lt = make_float3(L[0], L[1], L[2]);
    float4 lq = make_float4(L[3], L[4], L[5], L[6]);

    // rotate ref.t by rel.q
    float3 v = make_float3(lq.x, lq.y, lq.z);
    float3 uv = f3cross(v, rt);
    float3 uuv = f3cross(v, uv);
    float3 t = make_float3(lt.x + rt.x + 2.0f * (lq.w * uv.x + uuv.x),
                           lt.y + rt.y + 2.0f * (lq.w * uv.y + uuv.y),
                           lt.z + rt.z + 2.0f * (lq.w * uv.z + uuv.z));

    // quaternion product lq * rq (Hamilton, [x,y,z,w])
    float3 v1 = make_float3(lq.x, lq.y, lq.z);
    float3 v2 = make_float3(rq.x, rq.y, rq.z);
    float w  = lq.w * rq.w - (v1.x * v2.x + v1.y * v2.y + v1.z * v2.z);
    float3 cx = f3cross(v1, v2);
    float3 qv = make_float3(lq.w * v2.x + rq.w * v1.x + cx.x,
                            lq.w * v2.y + rq.w * v1.y + cx.y,
                            lq.w * v2.z + rq.w * v1.z + cx.z);

    g_comp[2 * i]     = make_float4(t.x, t.y, t.z, 0.0f);
    g_comp[2 * i + 1] = make_float4(qv.x, qv.y, qv.z, w);
}

// Main reprojection kernel: one thread per observation.
__global__ __launch_bounds__(256) void project_kernel(
    const float2* __restrict__ points_2d,
    const int*    __restrict__ camera_indices,
    const int2*   __restrict__ grouping_indices,
    const int*    __restrict__ point_indices,
    const float2* __restrict__ camera_pps,
    const float2* __restrict__ intrs,
    float2*       __restrict__ out)
{
    int i = blockIdx.x * blockDim.x + threadIdx.x;
    if (i >= NPTS) return;

    // Issue all independent loads up front (MLP)
    int2  gm  = __ldg(grouping_indices + i);
    int   pi  = __ldg(point_indices + i);
    int   ci  = __ldg(camera_indices + i);
    float2 obs = __ldg(points_2d + i);

    int base = (gm.x * NUM_POS + gm.y) * 2;
    float4 tc = g_comp[base];       // composed translation
    float4 q  = g_comp[base + 1];   // composed quaternion [x,y,z,w]
    float4 p  = g_pts[pi];          // 3D point (w = 0)

    float2 K  = __ldg(intrs + ci);
    float2 pp = __ldg(camera_pps + ci);

    // p_cam = rot(q, p) + t
    float3 v = make_float3(q.x, q.y, q.z);
    float3 p3 = make_float3(p.x, p.y, p.z);
    float3 uv = f3cross(v, p3);
    float3 uuv = f3cross(v, uv);
    float px = p3.x + 2.0f * (q.w * uv.x + uuv.x) + tc.x;
    float py = p3.y + 2.0f * (q.w * uv.y + uuv.y) + tc.y;
    float pz = p3.z + 2.0f * (q.w * uv.z + uuv.z) + tc.z;

    float inv_z = __fdividef(1.0f, pz);
    float2 r;
    r.x = fmaf(K.x, px * inv_z, pp.x) - obs.x;
    r.y = fmaf(K.y, py * inv_z, pp.y) - obs.y;
    out[i] = r;
}

extern "C" void kernel_launch(void* const* d_in, const int* in_sizes, int n_in,
                              void* d_out, int out_size) {
    // metadata.txt order:
    // 0 points_2d (float32, N*2)
    // 1 camera_indices (int32, N)
    // 2 grouping_indices (int32, N*2)
    // 3 point_indices (int32, N)
    // 4 camera_pps (float32, 8*2)
    // 5 intrs (float32, 8*2)
    // 6 points_3d (float32, NUM_PTS3D*3)
    // 7 ref_poses (float32, NUM_GROUPS*7)
    // 8 rel_poses (float32, 8*7)
    const float2* points_2d   = (const float2*)d_in[0];
    const int*    cam_idx     = (const int*)d_in[1];
    const int2*   grp_idx     = (const int2*)d_in[2];
    const int*    pt_idx      = (const int*)d_in[3];
    const float2* camera_pps  = (const float2*)d_in[4];
    const float2* intrs       = (const float2*)d_in[5];
    const float*  points_3d   = (const float*)d_in[6];
    const float*  ref_poses   = (const float*)d_in[7];
    const float*  rel_poses   = (const float*)d_in[8];
    float2* out = (float2*)d_out;

    pad_points_kernel<<<(NUM_PTS3D + 255) / 256, 256>>>(points_3d);
    compose_kernel<<<(NUM_GROUPS * NUM_POS + 255) / 256, 256>>>(ref_poses, rel_poses);
    project_kernel<<<(NPTS + 255) / 256, 256>>>(points_2d, cam_idx, grp_idx, pt_idx,
                                                camera_pps, intrs, out);
}

// round 4
// speedup vs baseline: 1.0400x; 1.0400x over previous
#include <cuda_runtime.h>
#include <cstdint>

// Problem constants (fixed by the reference generator)
#define NPTS        2000000
#define NUM_PTS3D   500000
#define NUM_GROUPS  10000
#define NUM_POS     8
#define NUM_CAMS    8

#define PAD_CHUNKS  (NUM_PTS3D / 4)            // 125000 (4 points per thread)
#define PAD_BLOCKS  ((PAD_CHUNKS + 255) / 256) // 489
#define COMP_N      (NUM_GROUPS * NUM_POS)     // 80000
#define COMP_BLOCKS ((COMP_N + 255) / 256)     // 313

// Scratch: composed pose table (80000 x {t(float4), q(float4)}) = 2.56 MB
// and padded 3D points (500000 x float4) = 8 MB. Both L2-resident.
__device__ float4 g_comp[COMP_N * 2];
__device__ float4 g_pts[NUM_PTS3D];

__device__ __forceinline__ float3 f3cross(float3 a, float3 b) {
    return make_float3(a.y * b.z - a.z * b.y,
                       a.z * b.x - a.x * b.z,
                       a.x * b.y - a.y * b.x);
}

// Fused prep kernel:
//  blocks [0, PAD_BLOCKS)                : pad points_3d [N,3] -> float4 table (4 pts/thread)
//  blocks [PAD_BLOCKS, PAD_BLOCKS+COMP_BLOCKS): compose ref x rel SE3 poses
__global__ __launch_bounds__(256) void prep_kernel(const float* __restrict__ p3d,
                                                   const float* __restrict__ ref_poses,
                                                   const float* __restrict__ rel_poses) {
    int b = blockIdx.x;
    if (b < PAD_BLOCKS) {
        int c = b * 256 + threadIdx.x;           // chunk of 4 points
        if (c >= PAD_CHUNKS) return;
        const float4* in = (const float4*)p3d;   // 375000 float4s
        float4 a = __ldg(in + 3 * c);
        float4 d = __ldg(in + 3 * c + 1);
        float4 e = __ldg(in + 3 * c + 2);
        int o = 4 * c;
        g_pts[o]     = make_float4(a.x, a.y, a.z, 0.0f);
        g_pts[o + 1] = make_float4(a.w, d.x, d.y, 0.0f);
        g_pts[o + 2] = make_float4(d.z, d.w, e.x, 0.0f);
        g_pts[o + 3] = make_float4(e.y, e.z, e.w, 0.0f);
        return;
    }

    int i = (b - PAD_BLOCKS) * 256 + threadIdx.x;
    if (i >= COMP_N) return;
    int g = i >> 3;          // group
    int m = i & 7;           // member
    const float* R = ref_poses + g * 7;
    const float* L = rel_poses + m * 7;

    float3 rt = make_float3(R[0], R[1], R[2]);
    float4 rq = make_float4(R[3], R[4], R[5], R[6]);
    float3 lt = make_float3(L[0], L[1], L[2]);
    float4 lq = make_float4(L[3], L[4], L[5], L[6]);

    // t = rel.t + rot(rel.q, ref.t)
    float3 v  = make_float3(lq.x, lq.y, lq.z);
    float3 uv = f3cross(v, rt);
    float3 uuv = f3cross(v, uv);
    float3 t = make_float3(lt.x + rt.x + 2.0f * (lq.w * uv.x + uuv.x),
                           lt.y + rt.y + 2.0f * (lq.w * uv.y + uuv.y),
                           lt.z + rt.z + 2.0f * (lq.w * uv.z + uuv.z));

    // q = lq * rq (Hamilton, [x,y,z,w])
    float3 v2 = make_float3(rq.x, rq.y, rq.z);
    float w  = lq.w * rq.w - (v.x * v2.x + v.y * v2.y + v.z * v2.z);
    float3 cx = f3cross(v, v2);
    float3 qv = make_float3(lq.w * v2.x + rq.w * v.x + cx.x,
                            lq.w * v2.y + rq.w * v.y + cx.y,
                            lq.w * v2.z + rq.w * v.z + cx.z);

    g_comp[2 * i]     = make_float4(t.x, t.y, t.z, 0.0f);
    g_comp[2 * i + 1] = make_float4(qv.x, qv.y, qv.z, w);
}

// Main reprojection: each thread handles 2 consecutive observations.
__global__ __launch_bounds__(256) void project_kernel(
    const float4* __restrict__ points_2d,       // pairs of obs
    const int2*   __restrict__ camera_indices,  // pairs
    const int4*   __restrict__ grouping_indices,// pairs of (g,m)
    const int2*   __restrict__ point_indices,   // pairs
    const float2* __restrict__ camera_pps,
    const float2* __restrict__ intrs,
    float4*       __restrict__ out)             // pairs of residuals
{
    int t = blockIdx.x * blockDim.x + threadIdx.x;
    if (t >= NPTS / 2) return;

    // All independent loads up front (MLP)
    int4   gm   = __ldg(grouping_indices + t);
    int2   pi   = __ldg(point_indices + t);
    int2   ci   = __ldg(camera_indices + t);
    float4 obs  = __ldg(points_2d + t);

    int base0 = (gm.x * NUM_POS + gm.y) * 2;
    int base1 = (gm.z * NUM_POS + gm.w) * 2;
    float4 tc0 = g_comp[base0];
    float4 q0  = g_comp[base0 + 1];
    float4 tc1 = g_comp[base1];
    float4 q1  = g_comp[base1 + 1];
    float4 p0  = g_pts[pi.x];
    float4 p1  = g_pts[pi.y];

    float2 K0  = __ldg(intrs + ci.x);
    float2 pp0 = __ldg(camera_pps + ci.x);
    float2 K1  = __ldg(intrs + ci.y);
    float2 pp1 = __ldg(camera_pps + ci.y);

    float4 r;
    {
        float3 v  = make_float3(q0.x, q0.y, q0.z);
        float3 p3 = make_float3(p0.x, p0.y, p0.z);
        float3 uv = f3cross(v, p3);
        float3 uuv = f3cross(v, uv);
        float px = p3.x + 2.0f * (q0.w * uv.x + uuv.x) + tc0.x;
        float py = p3.y + 2.0f * (q0.w * uv.y + uuv.y) + tc0.y;
        float pz = p3.z + 2.0f * (q0.w * uv.z + uuv.z) + tc0.z;
        float iz = __fdividef(1.0f, pz);
        r.x = fmaf(K0.x, px * iz, pp0.x) - obs.x;
        r.y = fmaf(K0.y, py * iz, pp0.y) - obs.y;
    }
    {
        float3 v  = make_float3(q1.x, q1.y, q1.z);
        float3 p3 = make_float3(p1.x, p1.y, p1.z);
        float3 uv = f3cross(v, p3);
        float3 uuv = f3cross(v, uv);
        float px = p3.x + 2.0f * (q1.w * uv.x + uuv.x) + tc1.x;
        float py = p3.y + 2.0f * (q1.w * uv.y + uuv.y) + tc1.y;
        float pz = p3.z + 2.0f * (q1.w * uv.z + uuv.z) + tc1.z;
        float iz = __fdividef(1.0f, pz);
        r.z = fmaf(K1.x, px * iz, pp1.x) - obs.z;
        r.w = fmaf(K1.y, py * iz, pp1.y) - obs.w;
    }
    out[t] = r;
}

extern "C" void kernel_launch(void* const* d_in, const int* in_sizes, int n_in,
                              void* d_out, int out_size) {
    const float* points_2d   = (const float*)d_in[0];
    const int*   cam_idx     = (const int*)d_in[1];
    const int*   grp_idx     = (const int*)d_in[2];
    const int*   pt_idx      = (const int*)d_in[3];
    const float* camera_pps  = (const float*)d_in[4];
    const float* intrs       = (const float*)d_in[5];
    const float* points_3d   = (const float*)d_in[6];
    const float* ref_poses   = (const float*)d_in[7];
    const float* rel_poses   = (const float*)d_in[8];

    prep_kernel<<<PAD_BLOCKS + COMP_BLOCKS, 256>>>(points_3d, ref_poses, rel_poses);
    project_kernel<<<(NPTS / 2 + 255) / 256, 256>>>(
        (const float4*)points_2d, (const int2*)cam_idx, (const int4*)grp_idx,
        (const int2*)pt_idx, (const float2*)camera_pps, (const float2*)intrs,
        (float4*)d_out);
}